// round 8
// baseline (speedup 1.0000x reference)
#include <cuda_runtime.h>
#include <cuda_fp16.h>
#include <cstdint>

#define Bn 16
#define Fn 257
#define FPAD 272
#define Tn 8000
#define NBn 64
#define TTILE 128
#define KSTEPS 17

// ---- scan config ----
#define NCH 8
#define CHUNK 1000
#define WARM 256
#define LOCAL (WARM + CHUNK)      // 1256 live local steps
#define STILE 64
#define NTILE 20
#define ROWST 68                  // floats per row (272B, 16B aligned)
#define O2ST 33
#define WBUF (32 * ROWST)         // 2176 floats per buffer per warp
#define O2OFF (8 * 2 * WBUF)      // 34816 floats
#define SCAN_SMEM ((8 * 2 * WBUF + 8 * 32 * O2ST) * 4)   // 173056 B

// ---- band GEMM config ----
#define AST 136
#define BST 280
#define OST 132
#define A_BYTES (FPAD * AST * 2)
#define B_BYTES (NBn * BST * 2)
#define SMEM_TOTAL (A_BYTES + B_BYTES)

// 65.8 MB fp16 scratch: g_vnr[b][f][t] = 0.1 * vnr (t-contiguous)
__device__ __align__(128) __half g_vnr[(size_t)Bn * Fn * Tn];
// pre-converted fp16 filterbank, padded [64][280]
__device__ __align__(128) __half g_fbh[NBn * BST];

__device__ __forceinline__ uint32_t smem_u32(const void* p) {
    uint32_t a;
    asm("{ .reg .u64 t; cvta.to.shared.u64 t, %1; cvt.u32.u64 %0, t; }" : "=r"(a) : "l"(p));
    return a;
}
__device__ __forceinline__ void cpasync16(uint32_t dst, const void* src, int sz) {
    asm volatile("cp.async.ca.shared.global [%0], [%1], 16, %2;" :: "r"(dst), "l"(src), "r"(sz));
}
__device__ __forceinline__ void cp_commit() { asm volatile("cp.async.commit_group;" ::: "memory"); }
__device__ __forceinline__ void cp_wait0()  { asm volatile("cp.async.wait_group 0;" ::: "memory"); }
__device__ __forceinline__ void cp_wait1()  { asm volatile("cp.async.wait_group 1;" ::: "memory"); }

__device__ __forceinline__ void ldsm_x4_t(uint32_t a[4], uint32_t addr) {
    asm volatile("ldmatrix.sync.aligned.m8n8.x4.trans.shared.b16 {%0,%1,%2,%3}, [%4];"
        : "=r"(a[0]), "=r"(a[1]), "=r"(a[2]), "=r"(a[3]) : "r"(addr));
}
__device__ __forceinline__ void ldsm_x4(uint32_t a[4], uint32_t addr) {
    asm volatile("ldmatrix.sync.aligned.m8n8.x4.shared.b16 {%0,%1,%2,%3}, [%4];"
        : "=r"(a[0]), "=r"(a[1]), "=r"(a[2]), "=r"(a[3]) : "r"(addr));
}
__device__ __forceinline__ void mma16816(float d[4], const uint32_t a[4], uint32_t b0, uint32_t b1) {
    asm volatile("mma.sync.aligned.m16n8k16.row.col.f32.f16.f16.f32 "
        "{%0,%1,%2,%3}, {%4,%5,%6,%7}, {%8,%9}, {%0,%1,%2,%3};"
        : "+f"(d[0]), "+f"(d[1]), "+f"(d[2]), "+f"(d[3])
        : "r"(a[0]), "r"(a[1]), "r"(a[2]), "r"(a[3]), "r"(b0), "r"(b1));
}
__device__ __forceinline__ float tanh_fast(float x) {
    float y; asm("tanh.approx.f32 %0, %1;" : "=f"(y) : "f"(x)); return y;
}

__device__ __forceinline__ float nf_step(float x, float nf, float rise, float fall, float fl) {
    float d  = x - nf;
    float cr = fmaf(rise, d, nf);
    float cf = fmaf(fall, d, nf);
    return fmaxf(fmaxf(cr, cf), fl);
}

// ============================================================
// K1: per-warp-pipelined staged scan -> g_vnr fp16 (0.1 * vnr)
// Blocks 0..143: warp = chunk, lane = chain. Coalesced cp.async.16
// tile loads, depth-2 pipeline (wait_group 1), NO block syncs.
// Blocks 144..151: fb fp32 -> fp16 conversion (fused launch).
// ============================================================
extern __shared__ float s_scan[];

__global__ __launch_bounds__(256, 1) void scan_kernel(
    const float* __restrict__ mag,
    const float* __restrict__ fbw,
    const float* __restrict__ p_ns,
    const float* __restrict__ p_rr,
    const float* __restrict__ p_rf)
{
    if (blockIdx.x >= Bn * 9) {
        // ---- fused fb conversion (8 blocks) ----
        int base = (blockIdx.x - Bn * 9) * 256 + threadIdx.x;
        for (int i = base; i < NBn * BST; i += 256 * 8) {
            int n = i / BST;
            int f = i - n * BST;
            g_fbh[i] = (f < Fn) ? __float2half_rn(__ldg(fbw + n * Fn + f)) : __float2half_rn(0.0f);
        }
        return;
    }

    const int bb = blockIdx.x / 9;
    const int fg = blockIdx.x % 9;
    const int c  = threadIdx.x >> 5;   // chunk (warp)
    const int l  = threadIdx.x & 31;   // chain lane

    const uint32_t sbase = smem_u32(s_scan);

    const float rise = 1.0f / (1.0f + expf(-__ldg(p_rr)));
    const float fall = 1.0f / (1.0f + expf(-__ldg(p_rf)));
    const float ns   = fabsf(__ldg(p_ns));

    const int fmine = fg * 32 + l;
    const bool fvalid = (fmine < Fn);

    float nf = 1.0f, fl_ = 0.0f;
    if (fvalid) {
        const size_t myrow = ((size_t)bb * Fn + fmine) * Tn;
        float mn = 3.4e38f;
        #pragma unroll
        for (int i = 0; i < 20; ++i) mn = fminf(mn, __ldg(mag + myrow + i));
        mn = fmaxf(mn, 1e-5f);
        nf = mn; fl_ = 0.5f * mn;
    }

    const int t0base = c * CHUNK - WARM;
    const float* magb = mag + (size_t)bb * Fn * Tn;

    #define ISSUE(k, sel) { \
        const int t0g = t0base + (k) * STILE; \
        const uint32_t dbase = sbase + (uint32_t)((c * 2 + (sel)) * WBUF * 4); \
        _Pragma("unroll") \
        for (int it = 0; it < 16; ++it) { \
            int o = l + 32 * it; \
            int m = o >> 4; \
            int seg = o & 15; \
            int tt = t0g + seg * 4; \
            int fm = fg * 32 + m; \
            int sz = (tt >= 0 && tt + 4 <= Tn && fm < Fn) ? 16 : 0; \
            int ttc = (tt < 0) ? 0 : ((tt + 4 > Tn) ? (Tn - 4) : tt); \
            int fmc = (fm < Fn) ? fm : 0; \
            cpasync16(dbase + (uint32_t)((m * ROWST + seg * 4) * 4), \
                      magb + (size_t)fmc * Tn + ttc, sz); \
        } \
        cp_commit(); }

    ISSUE(0, 0);
    ISSUE(1, 1);

    __half2 pend = __floats2half2_rn(0.f, 0.f);

    for (int k = 0; k < NTILE; ++k) {
        cp_wait1();
        __syncwarp();

        const float* srow = s_scan + (c * 2 + (k & 1)) * WBUF + l * ROWST;
        float* orow = s_scan + O2OFF + (c * 32 + l) * O2ST;

        #pragma unroll 8
        for (int j = 0; j < STILE; ++j) {
            const int i = k * STILE + j;
            if (i >= LOCAL) break;
            float x = srow[j];
            if (c > 0 || i >= WARM) {
                nf = nf_step(x, nf, rise, fall, fl_);
                if (i >= WARM) {
                    float o = __fdividef(x, fmaf(ns, nf, 1e-8f)) * 0.1f;
                    __half h = __float2half_rn(o);
                    if ((j & 1) == 0) {
                        pend = __half2half2(h);
                    } else {
                        pend = __halves2half2(__low2half(pend), h);
                        *reinterpret_cast<__half2*>(&orow[j >> 1]) = pend;
                    }
                }
            }
        }
        __syncwarp();

        if (k >= WARM / STILE) {
            const int ipair = k * STILE + 2 * l;
            const bool pv = (ipair >= WARM && ipair < LOCAL);
            const int tg = c * CHUNK + (ipair - WARM);
            #pragma unroll
            for (int m = 0; m < 32; ++m) {
                const int fm = fg * 32 + m;
                if (pv && fm < Fn) {
                    float v = s_scan[O2OFF + (c * 32 + m) * O2ST + l];
                    *reinterpret_cast<__half2*>(
                        g_vnr + ((size_t)bb * Fn + fm) * Tn + tg) =
                        *reinterpret_cast<__half2*>(&v);
                }
            }
        }
        __syncwarp();

        if (k + 2 < NTILE) ISSUE(k + 2, k & 1);
    }
    cp_wait0();
    #undef ISSUE
}

// ============================================================
// K2: HMMA band GEMM (unchanged from passing 103us version)
// ============================================================
extern __shared__ char k2_smem[];

__global__ __launch_bounds__(256, 2) void band_kernel(float* __restrict__ out)
{
    const int b   = blockIdx.y;
    const int t0  = blockIdx.x * TTILE;
    const int tid = threadIdx.x;
    const int wid = tid >> 5;
    const int lane = tid & 31;

    __half* As = reinterpret_cast<__half*>(k2_smem);             // [FPAD][AST]
    __half* Bs = reinterpret_cast<__half*>(k2_smem + A_BYTES);   // [NBn][BST]
    const uint32_t As_u = smem_u32(As);
    const uint32_t Bs_u = smem_u32(Bs);

    const size_t vbase = (size_t)b * Fn * Tn;
    #pragma unroll
    for (int it = 0; it < 17; ++it) {
        int i = tid + it * 256;
        int f = i >> 4;
        int c = i & 15;
        int t = t0 + c * 8;
        int sz = (f < Fn && t + 8 <= Tn) ? 16 : 0;
        int fc = (f < Fn) ? f : 0;
        int tc = (t + 8 <= Tn) ? t : 0;
        cpasync16(As_u + (uint32_t)((f * AST + c * 8) * 2),
                  g_vnr + vbase + (size_t)fc * Tn + tc, sz);
    }
    {
        const uint4* src = reinterpret_cast<const uint4*>(g_fbh);
        uint4* dst = reinterpret_cast<uint4*>(Bs);
        #pragma unroll
        for (int it = 0; it < 9; ++it) {
            int i = tid + it * 256;
            if (i < NBn * BST / 8) dst[i] = src[i];
        }
    }
    cp_commit();
    cp_wait0();
    __syncthreads();

    const int m0 = wid * 16;
    const int krow = (lane & 7) + ((lane >> 4) << 3);
    const int msel = ((lane >> 3) & 1) * 8;
    const uint32_t a_addr0 = As_u + (uint32_t)((krow * AST + m0 + msel) * 2);

    const int nrow = (lane & 7) + ((lane >> 4) << 3);
    const int ksel = ((lane >> 3) & 1) * 8;
    uint32_t b_addr0[4];
    #pragma unroll
    for (int j2 = 0; j2 < 4; ++j2)
        b_addr0[j2] = Bs_u + (uint32_t)(((j2 * 16 + nrow) * BST + ksel) * 2);

    float d[8][4];
    #pragma unroll
    for (int j = 0; j < 8; ++j)
        #pragma unroll
        for (int q = 0; q < 4; ++q) d[j][q] = 0.0f;

    for (int ks = 0; ks < KSTEPS; ++ks) {
        uint32_t a[4];
        ldsm_x4_t(a, a_addr0 + (uint32_t)(ks * 16 * AST * 2));
        #pragma unroll
        for (int j2 = 0; j2 < 4; ++j2) {
            uint32_t bbv[4];
            ldsm_x4(bbv, b_addr0[j2] + (uint32_t)(ks * 32));
            mma16816(d[j2 * 2],     a, bbv[0], bbv[1]);
            mma16816(d[j2 * 2 + 1], a, bbv[2], bbv[3]);
        }
    }

    __syncthreads();
    float* stg = reinterpret_cast<float*>(k2_smem);              // [NBn][OST]
    const int g  = lane >> 2;
    const int tp = lane & 3;
    #pragma unroll
    for (int j = 0; j < 8; ++j) {
        int n = j * 8 + 2 * tp;
        int t = m0 + g;
        stg[n * OST + t]           = d[j][0];
        stg[(n + 1) * OST + t]     = d[j][1];
        stg[n * OST + t + 8]       = d[j][2];
        stg[(n + 1) * OST + t + 8] = d[j][3];
    }
    __syncthreads();

    const int tmax = Tn - t0;
    float* ob = out + (size_t)b * NBn * Tn + t0;
    #pragma unroll
    for (int it = 0; it < 8; ++it) {
        int idx = tid + it * 256;
        int n = idx >> 5;
        int c = (idx & 31) * 4;
        if (c < tmax) {
            float4 v = *reinterpret_cast<float4*>(stg + n * OST + c);
            v.x = tanh_fast(v.x); v.y = tanh_fast(v.y);
            v.z = tanh_fast(v.z); v.w = tanh_fast(v.w);
            *reinterpret_cast<float4*>(ob + (size_t)n * Tn + c) = v;
        }
    }
}

// ============================================================
extern "C" void kernel_launch(void* const* d_in, const int* in_sizes, int n_in,
                              void* d_out, int out_size)
{
    const float* mag = (const float*)d_in[0];
    const float* fb  = (const float*)d_in[1];
    const float* ns  = (const float*)d_in[2];
    const float* rr  = (const float*)d_in[3];
    const float* rf  = (const float*)d_in[4];
    float* out = (float*)d_out;

    cudaFuncSetAttribute(scan_kernel, cudaFuncAttributeMaxDynamicSharedMemorySize, SCAN_SMEM);
    cudaFuncSetAttribute(band_kernel, cudaFuncAttributeMaxDynamicSharedMemorySize, SMEM_TOTAL);

    scan_kernel<<<Bn * 9 + 8, 256, SCAN_SMEM>>>(mag, fb, ns, rr, rf);

    dim3 grid((Tn + TTILE - 1) / TTILE, Bn);   // 63 x 16
    band_kernel<<<grid, 256, SMEM_TOTAL>>>(out);
}

// round 9
// speedup vs baseline: 1.1696x; 1.1696x over previous
#include <cuda_runtime.h>
#include <cuda_fp16.h>
#include <cstdint>

#define Bn 16
#define Fn 257
#define FPAD 272
#define Tn 8000
#define NBn 64
#define TTILE 128
#define KSTEPS 17

// ---- scan config ----
#define NCH 10
#define CHUNK 800
#define WARM 192
#define SCAN_THREADS (Bn * Fn * NCH)          // 41120
#define SCAN_BLOCKS ((SCAN_THREADS + 255) / 256)  // 161

// ---- band GEMM config ----
#define AST 136
#define BST 280
#define OST 132
#define A_BYTES (FPAD * AST * 2)
#define B_BYTES (NBn * BST * 2)
#define SMEM_TOTAL (A_BYTES + B_BYTES)

// 65.8 MB fp16 scratch: g_vnr[b][f][t] = 0.1 * vnr (t-contiguous)
__device__ __align__(128) __half g_vnr[(size_t)Bn * Fn * Tn];
// pre-converted fp16 filterbank, padded [64][280]
__device__ __align__(128) __half g_fbh[NBn * BST];

struct __align__(16) H8 { __half2 a, b, c, d; };

__device__ __forceinline__ uint32_t smem_u32(const void* p) {
    uint32_t a;
    asm("{ .reg .u64 t; cvta.to.shared.u64 t, %1; cvt.u32.u64 %0, t; }" : "=r"(a) : "l"(p));
    return a;
}
__device__ __forceinline__ void cpasync16(uint32_t dst, const void* src, int sz) {
    asm volatile("cp.async.ca.shared.global [%0], [%1], 16, %2;" :: "r"(dst), "l"(src), "r"(sz));
}
__device__ __forceinline__ void cp_commit() { asm volatile("cp.async.commit_group;" ::: "memory"); }
__device__ __forceinline__ void cp_wait0()  { asm volatile("cp.async.wait_group 0;" ::: "memory"); }

__device__ __forceinline__ void ldsm_x4_t(uint32_t a[4], uint32_t addr) {
    asm volatile("ldmatrix.sync.aligned.m8n8.x4.trans.shared.b16 {%0,%1,%2,%3}, [%4];"
        : "=r"(a[0]), "=r"(a[1]), "=r"(a[2]), "=r"(a[3]) : "r"(addr));
}
__device__ __forceinline__ void ldsm_x4(uint32_t a[4], uint32_t addr) {
    asm volatile("ldmatrix.sync.aligned.m8n8.x4.shared.b16 {%0,%1,%2,%3}, [%4];"
        : "=r"(a[0]), "=r"(a[1]), "=r"(a[2]), "=r"(a[3]) : "r"(addr));
}
__device__ __forceinline__ void mma16816(float d[4], const uint32_t a[4], uint32_t b0, uint32_t b1) {
    asm volatile("mma.sync.aligned.m16n8k16.row.col.f32.f16.f16.f32 "
        "{%0,%1,%2,%3}, {%4,%5,%6,%7}, {%8,%9}, {%0,%1,%2,%3};"
        : "+f"(d[0]), "+f"(d[1]), "+f"(d[2]), "+f"(d[3])
        : "r"(a[0]), "r"(a[1]), "r"(a[2]), "r"(a[3]), "r"(b0), "r"(b1));
}
__device__ __forceinline__ float tanh_fast(float x) {
    float y; asm("tanh.approx.f32 %0, %1;" : "=f"(y) : "f"(x)); return y;
}

__device__ __forceinline__ float nf_step(float x, float nf, float rise, float fall, float fl) {
    float d  = x - nf;
    float cr = fmaf(rise, d, nf);
    float cf = fmaf(fall, d, nf);
    return fmaxf(fmaxf(cr, cf), fl);
}

// ============================================================
// K1: chunked scan -> fp16 scratch [b][f][t], 16B packed stores.
// Blocks >= SCAN_BLOCKS do the fb fp32->fp16 conversion (fused).
// ============================================================
__global__ __launch_bounds__(256) void scan_kernel(
    const float* __restrict__ mag,
    const float* __restrict__ fbw,
    const float* __restrict__ p_ns,
    const float* __restrict__ p_rr,
    const float* __restrict__ p_rf)
{
    if (blockIdx.x >= SCAN_BLOCKS) {
        int base = (blockIdx.x - SCAN_BLOCKS) * 256 + threadIdx.x;
        for (int i = base; i < NBn * BST; i += 256 * 8) {
            int n = i / BST;
            int f = i - n * BST;
            g_fbh[i] = (f < Fn) ? __float2half_rn(__ldg(fbw + n * Fn + f)) : __float2half_rn(0.0f);
        }
        return;
    }

    int tid = blockIdx.x * 256 + threadIdx.x;
    if (tid >= SCAN_THREADS) return;
    int chunk = tid % NCH;
    int chain = tid / NCH;

    const float rise = 1.0f / (1.0f + expf(-__ldg(p_rr)));
    const float fall = 1.0f / (1.0f + expf(-__ldg(p_rf)));
    const float ns10 = 10.0f * fabsf(__ldg(p_ns));

    size_t base = (size_t)chain * Tn;
    const float4* gm = reinterpret_cast<const float4*>(mag + base);
    H8* gv8 = reinterpret_cast<H8*>(g_vnr + base);

    float mn = 3.4e38f;
    #pragma unroll
    for (int i = 0; i < 20; ++i) mn = fminf(mn, __ldg(mag + base + i));
    mn = fmaxf(mn, 1e-5f);
    const float fl = 0.5f * mn;
    float nf = mn;

    const int t0 = chunk * CHUNK;
    const int tw = (chunk == 0) ? 0 : (t0 - WARM);

    for (int q = (tw >> 2); q < (t0 >> 2); ++q) {
        float4 v = gm[q];
        nf = nf_step(v.x, nf, rise, fall, fl);
        nf = nf_step(v.y, nf, rise, fall, fl);
        nf = nf_step(v.z, nf, rise, fall, fl);
        nf = nf_step(v.w, nf, rise, fall, fl);
    }

    const int q0 = t0 >> 2;
    float4 b0 = gm[q0], b1 = gm[q0 + 1], b2 = gm[q0 + 2], b3 = gm[q0 + 3];

    // process 8 t-steps (two float4) -> one 16B store
    #define EMIT8(ca, cb, idx8) { \
        float o0, o1, o2, o3, o4, o5, o6, o7; \
        nf = nf_step(ca.x, nf, rise, fall, fl); o0 = __fdividef(ca.x, fmaf(ns10, nf, 1e-7f)); \
        nf = nf_step(ca.y, nf, rise, fall, fl); o1 = __fdividef(ca.y, fmaf(ns10, nf, 1e-7f)); \
        nf = nf_step(ca.z, nf, rise, fall, fl); o2 = __fdividef(ca.z, fmaf(ns10, nf, 1e-7f)); \
        nf = nf_step(ca.w, nf, rise, fall, fl); o3 = __fdividef(ca.w, fmaf(ns10, nf, 1e-7f)); \
        nf = nf_step(cb.x, nf, rise, fall, fl); o4 = __fdividef(cb.x, fmaf(ns10, nf, 1e-7f)); \
        nf = nf_step(cb.y, nf, rise, fall, fl); o5 = __fdividef(cb.y, fmaf(ns10, nf, 1e-7f)); \
        nf = nf_step(cb.z, nf, rise, fall, fl); o6 = __fdividef(cb.z, fmaf(ns10, nf, 1e-7f)); \
        nf = nf_step(cb.w, nf, rise, fall, fl); o7 = __fdividef(cb.w, fmaf(ns10, nf, 1e-7f)); \
        H8 pk; \
        pk.a = __floats2half2_rn(o0, o1); pk.b = __floats2half2_rn(o2, o3); \
        pk.c = __floats2half2_rn(o4, o5); pk.d = __floats2half2_rn(o6, o7); \
        gv8[idx8] = pk; }

    for (int i = 0; i < CHUNK / 4; i += 4) {
        float4 c0 = b0, c1 = b1, c2 = b2, c3 = b3;
        if (i + 8 <= CHUNK / 4) {
            b0 = gm[q0 + i + 4]; b1 = gm[q0 + i + 5];
            b2 = gm[q0 + i + 6]; b3 = gm[q0 + i + 7];
        }
        EMIT8(c0, c1, (q0 + i) >> 1);
        EMIT8(c2, c3, ((q0 + i) >> 1) + 1);
    }
    #undef EMIT8
}

// ============================================================
// K2: HMMA band GEMM (unchanged, proven 30.4us)
// ============================================================
extern __shared__ char k2_smem[];

__global__ __launch_bounds__(256, 2) void band_kernel(float* __restrict__ out)
{
    const int b   = blockIdx.y;
    const int t0  = blockIdx.x * TTILE;
    const int tid = threadIdx.x;
    const int wid = tid >> 5;
    const int lane = tid & 31;

    __half* As = reinterpret_cast<__half*>(k2_smem);             // [FPAD][AST]
    __half* Bs = reinterpret_cast<__half*>(k2_smem + A_BYTES);   // [NBn][BST]
    const uint32_t As_u = smem_u32(As);
    const uint32_t Bs_u = smem_u32(Bs);

    const size_t vbase = (size_t)b * Fn * Tn;
    #pragma unroll
    for (int it = 0; it < 17; ++it) {
        int i = tid + it * 256;
        int f = i >> 4;
        int c = i & 15;
        int t = t0 + c * 8;
        int sz = (f < Fn && t + 8 <= Tn) ? 16 : 0;
        int fc = (f < Fn) ? f : 0;
        int tc = (t + 8 <= Tn) ? t : 0;
        cpasync16(As_u + (uint32_t)((f * AST + c * 8) * 2),
                  g_vnr + vbase + (size_t)fc * Tn + tc, sz);
    }
    {
        const uint4* src = reinterpret_cast<const uint4*>(g_fbh);
        uint4* dst = reinterpret_cast<uint4*>(Bs);
        #pragma unroll
        for (int it = 0; it < 9; ++it) {
            int i = tid + it * 256;
            if (i < NBn * BST / 8) dst[i] = src[i];
        }
    }
    cp_commit();
    cp_wait0();
    __syncthreads();

    const int m0 = wid * 16;
    const int krow = (lane & 7) + ((lane >> 4) << 3);
    const int msel = ((lane >> 3) & 1) * 8;
    const uint32_t a_addr0 = As_u + (uint32_t)((krow * AST + m0 + msel) * 2);

    const int nrow = (lane & 7) + ((lane >> 4) << 3);
    const int ksel = ((lane >> 3) & 1) * 8;
    uint32_t b_addr0[4];
    #pragma unroll
    for (int j2 = 0; j2 < 4; ++j2)
        b_addr0[j2] = Bs_u + (uint32_t)(((j2 * 16 + nrow) * BST + ksel) * 2);

    float d[8][4];
    #pragma unroll
    for (int j = 0; j < 8; ++j)
        #pragma unroll
        for (int q = 0; q < 4; ++q) d[j][q] = 0.0f;

    for (int ks = 0; ks < KSTEPS; ++ks) {
        uint32_t a[4];
        ldsm_x4_t(a, a_addr0 + (uint32_t)(ks * 16 * AST * 2));
        #pragma unroll
        for (int j2 = 0; j2 < 4; ++j2) {
            uint32_t bbv[4];
            ldsm_x4(bbv, b_addr0[j2] + (uint32_t)(ks * 32));
            mma16816(d[j2 * 2],     a, bbv[0], bbv[1]);
            mma16816(d[j2 * 2 + 1], a, bbv[2], bbv[3]);
        }
    }

    __syncthreads();
    float* stg = reinterpret_cast<float*>(k2_smem);              // [NBn][OST]
    const int g  = lane >> 2;
    const int tp = lane & 3;
    #pragma unroll
    for (int j = 0; j < 8; ++j) {
        int n = j * 8 + 2 * tp;
        int t = m0 + g;
        stg[n * OST + t]           = d[j][0];
        stg[(n + 1) * OST + t]     = d[j][1];
        stg[n * OST + t + 8]       = d[j][2];
        stg[(n + 1) * OST + t + 8] = d[j][3];
    }
    __syncthreads();

    const int tmax = Tn - t0;
    float* ob = out + (size_t)b * NBn * Tn + t0;
    #pragma unroll
    for (int it = 0; it < 8; ++it) {
        int idx = tid + it * 256;
        int n = idx >> 5;
        int c = (idx & 31) * 4;
        if (c < tmax) {
            float4 v = *reinterpret_cast<float4*>(stg + n * OST + c);
            v.x = tanh_fast(v.x); v.y = tanh_fast(v.y);
            v.z = tanh_fast(v.z); v.w = tanh_fast(v.w);
            *reinterpret_cast<float4*>(ob + (size_t)n * Tn + c) = v;
        }
    }
}

// ============================================================
extern "C" void kernel_launch(void* const* d_in, const int* in_sizes, int n_in,
                              void* d_out, int out_size)
{
    const float* mag = (const float*)d_in[0];
    const float* fb  = (const float*)d_in[1];
    const float* ns  = (const float*)d_in[2];
    const float* rr  = (const float*)d_in[3];
    const float* rf  = (const float*)d_in[4];
    float* out = (float*)d_out;

    cudaFuncSetAttribute(band_kernel, cudaFuncAttributeMaxDynamicSharedMemorySize, SMEM_TOTAL);

    scan_kernel<<<SCAN_BLOCKS + 8, 256>>>(mag, fb, ns, rr, rf);

    dim3 grid((Tn + TTILE - 1) / TTILE, Bn);   // 63 x 16
    band_kernel<<<grid, 256, SMEM_TOTAL>>>(out);
}

// round 10
// speedup vs baseline: 1.4094x; 1.2051x over previous
#include <cuda_runtime.h>
#include <cuda_fp16.h>
#include <cstdint>

#define Bn 16
#define Fn 257
#define FPAD 272
#define Tn 8000
#define NBn 64
#define TTILE 128
#define KSTEPS 17

// ---- scan config (r7-proven parallelism, shorter warmup) ----
#define NCH 20
#define CHUNK 400
#define WARM 160
#define SCAN_THREADS (Bn * Fn * NCH)               // 82240
#define SCAN_BLOCKS ((SCAN_THREADS + 255) / 256)   // 322

// ---- band GEMM config ----
#define AST 136
#define BST 280
#define OST 132
#define A_BYTES (FPAD * AST * 2)
#define B_BYTES (NBn * BST * 2)
#define SMEM_TOTAL (A_BYTES + B_BYTES)

// 65.8 MB fp16 scratch: g_vnr[b][f][t] = vnr/10 (t-contiguous)
__device__ __align__(128) __half g_vnr[(size_t)Bn * Fn * Tn];
// pre-converted fp16 filterbank, padded [64][280]
__device__ __align__(128) __half g_fbh[NBn * BST];

struct __align__(8) H4 { __half2 a, b; };

__device__ __forceinline__ uint32_t smem_u32(const void* p) {
    uint32_t a;
    asm("{ .reg .u64 t; cvta.to.shared.u64 t, %1; cvt.u32.u64 %0, t; }" : "=r"(a) : "l"(p));
    return a;
}
__device__ __forceinline__ void cpasync16(uint32_t dst, const void* src, int sz) {
    asm volatile("cp.async.ca.shared.global [%0], [%1], 16, %2;" :: "r"(dst), "l"(src), "r"(sz));
}
__device__ __forceinline__ void cp_commit() { asm volatile("cp.async.commit_group;" ::: "memory"); }
__device__ __forceinline__ void cp_wait0()  { asm volatile("cp.async.wait_group 0;" ::: "memory"); }

__device__ __forceinline__ void ldsm_x4_t(uint32_t a[4], uint32_t addr) {
    asm volatile("ldmatrix.sync.aligned.m8n8.x4.trans.shared.b16 {%0,%1,%2,%3}, [%4];"
        : "=r"(a[0]), "=r"(a[1]), "=r"(a[2]), "=r"(a[3]) : "r"(addr));
}
__device__ __forceinline__ void ldsm_x4(uint32_t a[4], uint32_t addr) {
    asm volatile("ldmatrix.sync.aligned.m8n8.x4.shared.b16 {%0,%1,%2,%3}, [%4];"
        : "=r"(a[0]), "=r"(a[1]), "=r"(a[2]), "=r"(a[3]) : "r"(addr));
}
__device__ __forceinline__ void mma16816(float d[4], const uint32_t a[4], uint32_t b0, uint32_t b1) {
    asm volatile("mma.sync.aligned.m16n8k16.row.col.f32.f16.f16.f32 "
        "{%0,%1,%2,%3}, {%4,%5,%6,%7}, {%8,%9}, {%0,%1,%2,%3};"
        : "+f"(d[0]), "+f"(d[1]), "+f"(d[2]), "+f"(d[3])
        : "r"(a[0]), "r"(a[1]), "r"(a[2]), "r"(a[3]), "r"(b0), "r"(b1));
}
__device__ __forceinline__ float tanh_fast(float x) {
    float y; asm("tanh.approx.f32 %0, %1;" : "=f"(y) : "f"(x)); return y;
}

__device__ __forceinline__ float nf_step(float x, float nf, float rise, float fall, float fl) {
    float d  = x - nf;
    float cr = fmaf(rise, d, nf);
    float cf = fmaf(fall, d, nf);
    return fmaxf(fmaxf(cr, cf), fl);
}

// ============================================================
// K1: chunked scan -> fp16 scratch [b][f][t] (vnr/10)
// 20 chunks/chain (82K threads), 160-step warmup, depth-4 prefetch.
// Blocks >= SCAN_BLOCKS do the fb fp32->fp16 conversion (fused).
// ============================================================
__global__ __launch_bounds__(256) void scan_kernel(
    const float* __restrict__ mag,
    const float* __restrict__ fbw,
    const float* __restrict__ p_ns,
    const float* __restrict__ p_rr,
    const float* __restrict__ p_rf)
{
    if (blockIdx.x >= SCAN_BLOCKS) {
        int base = (blockIdx.x - SCAN_BLOCKS) * 256 + threadIdx.x;
        for (int i = base; i < NBn * BST; i += 256 * 8) {
            int n = i / BST;
            int f = i - n * BST;
            g_fbh[i] = (f < Fn) ? __float2half_rn(__ldg(fbw + n * Fn + f)) : __float2half_rn(0.0f);
        }
        return;
    }

    int tid = blockIdx.x * 256 + threadIdx.x;
    if (tid >= SCAN_THREADS) return;
    int chunk = tid % NCH;
    int chain = tid / NCH;

    const float rise = 1.0f / (1.0f + expf(-__ldg(p_rr)));
    const float fall = 1.0f / (1.0f + expf(-__ldg(p_rf)));
    const float ns10 = 10.0f * fabsf(__ldg(p_ns));

    size_t base = (size_t)chain * Tn;
    const float4* gm = reinterpret_cast<const float4*>(mag + base);
    H4* gv = reinterpret_cast<H4*>(g_vnr + base);

    float mn = 3.4e38f;
    #pragma unroll
    for (int i = 0; i < 20; ++i) mn = fminf(mn, __ldg(mag + base + i));
    mn = fmaxf(mn, 1e-5f);
    const float fl = 0.5f * mn;
    float nf = mn;

    const int t0 = chunk * CHUNK;
    const int tw = (chunk == 0) ? 0 : (t0 - WARM);

    for (int q = (tw >> 2); q < (t0 >> 2); ++q) {
        float4 v = gm[q];
        nf = nf_step(v.x, nf, rise, fall, fl);
        nf = nf_step(v.y, nf, rise, fall, fl);
        nf = nf_step(v.z, nf, rise, fall, fl);
        nf = nf_step(v.w, nf, rise, fall, fl);
    }

    const int q0 = t0 >> 2;
    float4 b0 = gm[q0], b1 = gm[q0 + 1], b2 = gm[q0 + 2], b3 = gm[q0 + 3];

    #define EMIT4(c, idx) { \
        float o0, o1, o2, o3; \
        nf = nf_step(c.x, nf, rise, fall, fl); o0 = __fdividef(c.x, fmaf(ns10, nf, 1e-7f)); \
        nf = nf_step(c.y, nf, rise, fall, fl); o1 = __fdividef(c.y, fmaf(ns10, nf, 1e-7f)); \
        nf = nf_step(c.z, nf, rise, fall, fl); o2 = __fdividef(c.z, fmaf(ns10, nf, 1e-7f)); \
        nf = nf_step(c.w, nf, rise, fall, fl); o3 = __fdividef(c.w, fmaf(ns10, nf, 1e-7f)); \
        H4 st; st.a = __floats2half2_rn(o0, o1); st.b = __floats2half2_rn(o2, o3); \
        gv[idx] = st; }

    for (int i = 0; i < CHUNK / 4; i += 4) {
        float4 c0 = b0, c1 = b1, c2 = b2, c3 = b3;
        if (i + 8 <= CHUNK / 4) {
            b0 = gm[q0 + i + 4]; b1 = gm[q0 + i + 5];
            b2 = gm[q0 + i + 6]; b3 = gm[q0 + i + 7];
        }
        EMIT4(c0, q0 + i);
        EMIT4(c1, q0 + i + 1);
        EMIT4(c2, q0 + i + 2);
        EMIT4(c3, q0 + i + 3);
    }
    #undef EMIT4
}

// ============================================================
// K2: HMMA band GEMM (proven core; B-tile now via cp.async too)
// ============================================================
extern __shared__ char k2_smem[];

__global__ __launch_bounds__(256, 2) void band_kernel(float* __restrict__ out)
{
    const int b   = blockIdx.y;
    const int t0  = blockIdx.x * TTILE;
    const int tid = threadIdx.x;
    const int wid = tid >> 5;
    const int lane = tid & 31;

    __half* As = reinterpret_cast<__half*>(k2_smem);             // [FPAD][AST]
    __half* Bs = reinterpret_cast<__half*>(k2_smem + A_BYTES);   // [NBn][BST]
    const uint32_t As_u = smem_u32(As);
    const uint32_t Bs_u = smem_u32(Bs);

    const size_t vbase = (size_t)b * Fn * Tn;
    #pragma unroll
    for (int it = 0; it < 17; ++it) {
        int i = tid + it * 256;
        int f = i >> 4;
        int c = i & 15;
        int t = t0 + c * 8;
        int sz = (f < Fn && t + 8 <= Tn) ? 16 : 0;
        int fc = (f < Fn) ? f : 0;
        int tc = (t + 8 <= Tn) ? t : 0;
        cpasync16(As_u + (uint32_t)((f * AST + c * 8) * 2),
                  g_vnr + vbase + (size_t)fc * Tn + tc, sz);
    }
    #pragma unroll
    for (int it = 0; it < 9; ++it) {
        int i = tid + it * 256;
        if (i < NBn * BST / 8)
            cpasync16(Bs_u + (uint32_t)(i * 16), g_fbh + i * 8, 16);
    }
    cp_commit();
    cp_wait0();
    __syncthreads();

    const int m0 = wid * 16;
    const int krow = (lane & 7) + ((lane >> 4) << 3);
    const int msel = ((lane >> 3) & 1) * 8;
    const uint32_t a_addr0 = As_u + (uint32_t)((krow * AST + m0 + msel) * 2);

    const int nrow = (lane & 7) + ((lane >> 4) << 3);
    const int ksel = ((lane >> 3) & 1) * 8;
    uint32_t b_addr0[4];
    #pragma unroll
    for (int j2 = 0; j2 < 4; ++j2)
        b_addr0[j2] = Bs_u + (uint32_t)(((j2 * 16 + nrow) * BST + ksel) * 2);

    float d[8][4];
    #pragma unroll
    for (int j = 0; j < 8; ++j)
        #pragma unroll
        for (int q = 0; q < 4; ++q) d[j][q] = 0.0f;

    for (int ks = 0; ks < KSTEPS; ++ks) {
        uint32_t a[4];
        ldsm_x4_t(a, a_addr0 + (uint32_t)(ks * 16 * AST * 2));
        #pragma unroll
        for (int j2 = 0; j2 < 4; ++j2) {
            uint32_t bbv[4];
            ldsm_x4(bbv, b_addr0[j2] + (uint32_t)(ks * 32));
            mma16816(d[j2 * 2],     a, bbv[0], bbv[1]);
            mma16816(d[j2 * 2 + 1], a, bbv[2], bbv[3]);
        }
    }

    __syncthreads();
    float* stg = reinterpret_cast<float*>(k2_smem);              // [NBn][OST]
    const int g  = lane >> 2;
    const int tp = lane & 3;
    #pragma unroll
    for (int j = 0; j < 8; ++j) {
        int n = j * 8 + 2 * tp;
        int t = m0 + g;
        stg[n * OST + t]           = d[j][0];
        stg[(n + 1) * OST + t]     = d[j][1];
        stg[n * OST + t + 8]       = d[j][2];
        stg[(n + 1) * OST + t + 8] = d[j][3];
    }
    __syncthreads();

    const int tmax = Tn - t0;
    float* ob = out + (size_t)b * NBn * Tn + t0;
    #pragma unroll
    for (int it = 0; it < 8; ++it) {
        int idx = tid + it * 256;
        int n = idx >> 5;
        int c = (idx & 31) * 4;
        if (c < tmax) {
            float4 v = *reinterpret_cast<float4*>(stg + n * OST + c);
            v.x = tanh_fast(v.x); v.y = tanh_fast(v.y);
            v.z = tanh_fast(v.z); v.w = tanh_fast(v.w);
            *reinterpret_cast<float4*>(ob + (size_t)n * Tn + c) = v;
        }
    }
}

// ============================================================
extern "C" void kernel_launch(void* const* d_in, const int* in_sizes, int n_in,
                              void* d_out, int out_size)
{
    const float* mag = (const float*)d_in[0];
    const float* fb  = (const float*)d_in[1];
    const float* ns  = (const float*)d_in[2];
    const float* rr  = (const float*)d_in[3];
    const float* rf  = (const float*)d_in[4];
    float* out = (float*)d_out;

    cudaFuncSetAttribute(band_kernel, cudaFuncAttributeMaxDynamicSharedMemorySize, SMEM_TOTAL);

    scan_kernel<<<SCAN_BLOCKS + 8, 256>>>(mag, fb, ns, rr, rf);

    dim3 grid((Tn + TTILE - 1) / TTILE, Bn);   // 63 x 16
    band_kernel<<<grid, 256, SMEM_TOTAL>>>(out);
}

// round 11
// speedup vs baseline: 1.4414x; 1.0227x over previous
#include <cuda_runtime.h>
#include <cuda_fp16.h>
#include <cstdint>

#define Bn 16
#define Fn 257
#define FPAD 272
#define Tn 8000
#define NBn 64
#define TTILE 128
#define KSTEPS 17

// ---- scan config ----
#define NCH 20
#define CHUNK 400
#define WARM 128
#define SCAN_THREADS (Bn * Fn * NCH)               // 82240
#define SCAN_BLOCKS ((SCAN_THREADS + 255) / 256)   // 322

// ---- band GEMM config ----
#define AST 136
#define BST 280
#define OST 132
#define A_BYTES (FPAD * AST * 2)
#define B_BYTES (NBn * BST * 2)
#define SMEM_TOTAL (A_BYTES + B_BYTES)

// 65.8 MB fp16 scratch: g_vnr[b][f][t] = vnr/10 (t-contiguous)
__device__ __align__(128) __half g_vnr[(size_t)Bn * Fn * Tn];
// pre-converted fp16 filterbank, padded [64][280]
__device__ __align__(128) __half g_fbh[NBn * BST];

struct __align__(16) H8 { __half2 a, b, c, d; };

__device__ __forceinline__ uint32_t smem_u32(const void* p) {
    uint32_t a;
    asm("{ .reg .u64 t; cvta.to.shared.u64 t, %1; cvt.u32.u64 %0, t; }" : "=r"(a) : "l"(p));
    return a;
}
__device__ __forceinline__ void cpasync16(uint32_t dst, const void* src, int sz) {
    asm volatile("cp.async.ca.shared.global [%0], [%1], 16, %2;" :: "r"(dst), "l"(src), "r"(sz));
}
__device__ __forceinline__ void cp_commit() { asm volatile("cp.async.commit_group;" ::: "memory"); }
__device__ __forceinline__ void cp_wait0()  { asm volatile("cp.async.wait_group 0;" ::: "memory"); }

__device__ __forceinline__ void ldsm_x4_t(uint32_t a[4], uint32_t addr) {
    asm volatile("ldmatrix.sync.aligned.m8n8.x4.trans.shared.b16 {%0,%1,%2,%3}, [%4];"
        : "=r"(a[0]), "=r"(a[1]), "=r"(a[2]), "=r"(a[3]) : "r"(addr));
}
__device__ __forceinline__ void ldsm_x4(uint32_t a[4], uint32_t addr) {
    asm volatile("ldmatrix.sync.aligned.m8n8.x4.shared.b16 {%0,%1,%2,%3}, [%4];"
        : "=r"(a[0]), "=r"(a[1]), "=r"(a[2]), "=r"(a[3]) : "r"(addr));
}
__device__ __forceinline__ void mma16816(float d[4], const uint32_t a[4], uint32_t b0, uint32_t b1) {
    asm volatile("mma.sync.aligned.m16n8k16.row.col.f32.f16.f16.f32 "
        "{%0,%1,%2,%3}, {%4,%5,%6,%7}, {%8,%9}, {%0,%1,%2,%3};"
        : "+f"(d[0]), "+f"(d[1]), "+f"(d[2]), "+f"(d[3])
        : "r"(a[0]), "r"(a[1]), "r"(a[2]), "r"(a[3]), "r"(b0), "r"(b1));
}
__device__ __forceinline__ float tanh_fast(float x) {
    float y; asm("tanh.approx.f32 %0, %1;" : "=f"(y) : "f"(x)); return y;
}

__device__ __forceinline__ float nf_step(float x, float nf, float rise, float fall, float fl) {
    float d  = x - nf;
    float cr = fmaf(rise, d, nf);
    float cf = fmaf(fall, d, nf);
    return fmaxf(fmaxf(cr, cf), fl);
}

// ============================================================
// K1: chunked scan -> fp16 scratch [b][f][t] (vnr/10)
// NCH=20 (82K threads), WARM=128, depth-4 float4 prefetch,
// 16B H8 packed stores. Blocks >= SCAN_BLOCKS: fused fb conversion.
// ============================================================
__global__ __launch_bounds__(256) void scan_kernel(
    const float* __restrict__ mag,
    const float* __restrict__ fbw,
    const float* __restrict__ p_ns,
    const float* __restrict__ p_rr,
    const float* __restrict__ p_rf)
{
    if (blockIdx.x >= SCAN_BLOCKS) {
        int base = (blockIdx.x - SCAN_BLOCKS) * 256 + threadIdx.x;
        for (int i = base; i < NBn * BST; i += 256 * 8) {
            int n = i / BST;
            int f = i - n * BST;
            g_fbh[i] = (f < Fn) ? __float2half_rn(__ldg(fbw + n * Fn + f)) : __float2half_rn(0.0f);
        }
        return;
    }

    int tid = blockIdx.x * 256 + threadIdx.x;
    if (tid >= SCAN_THREADS) return;
    int chunk = tid % NCH;
    int chain = tid / NCH;

    const float rise = 1.0f / (1.0f + expf(-__ldg(p_rr)));
    const float fall = 1.0f / (1.0f + expf(-__ldg(p_rf)));
    const float ns10 = 10.0f * fabsf(__ldg(p_ns));

    size_t base = (size_t)chain * Tn;
    const float4* gm = reinterpret_cast<const float4*>(mag + base);
    H8* gv8 = reinterpret_cast<H8*>(g_vnr + base);

    float mn = 3.4e38f;
    #pragma unroll
    for (int i = 0; i < 20; ++i) mn = fminf(mn, __ldg(mag + base + i));
    mn = fmaxf(mn, 1e-5f);
    const float fl = 0.5f * mn;
    float nf = mn;

    const int t0 = chunk * CHUNK;
    const int tw = (chunk == 0) ? 0 : (t0 - WARM);

    for (int q = (tw >> 2); q < (t0 >> 2); ++q) {
        float4 v = gm[q];
        nf = nf_step(v.x, nf, rise, fall, fl);
        nf = nf_step(v.y, nf, rise, fall, fl);
        nf = nf_step(v.z, nf, rise, fall, fl);
        nf = nf_step(v.w, nf, rise, fall, fl);
    }

    const int q0 = t0 >> 2;
    float4 b0 = gm[q0], b1 = gm[q0 + 1], b2 = gm[q0 + 2], b3 = gm[q0 + 3];

    // 8 t-steps (two float4) -> one 16B store
    #define EMIT8(ca, cb, idx8) { \
        float o0, o1, o2, o3, o4, o5, o6, o7; \
        nf = nf_step(ca.x, nf, rise, fall, fl); o0 = __fdividef(ca.x, fmaf(ns10, nf, 1e-7f)); \
        nf = nf_step(ca.y, nf, rise, fall, fl); o1 = __fdividef(ca.y, fmaf(ns10, nf, 1e-7f)); \
        nf = nf_step(ca.z, nf, rise, fall, fl); o2 = __fdividef(ca.z, fmaf(ns10, nf, 1e-7f)); \
        nf = nf_step(ca.w, nf, rise, fall, fl); o3 = __fdividef(ca.w, fmaf(ns10, nf, 1e-7f)); \
        nf = nf_step(cb.x, nf, rise, fall, fl); o4 = __fdividef(cb.x, fmaf(ns10, nf, 1e-7f)); \
        nf = nf_step(cb.y, nf, rise, fall, fl); o5 = __fdividef(cb.y, fmaf(ns10, nf, 1e-7f)); \
        nf = nf_step(cb.z, nf, rise, fall, fl); o6 = __fdividef(cb.z, fmaf(ns10, nf, 1e-7f)); \
        nf = nf_step(cb.w, nf, rise, fall, fl); o7 = __fdividef(cb.w, fmaf(ns10, nf, 1e-7f)); \
        H8 pk; \
        pk.a = __floats2half2_rn(o0, o1); pk.b = __floats2half2_rn(o2, o3); \
        pk.c = __floats2half2_rn(o4, o5); pk.d = __floats2half2_rn(o6, o7); \
        gv8[idx8] = pk; }

    for (int i = 0; i < CHUNK / 4; i += 4) {
        float4 c0 = b0, c1 = b1, c2 = b2, c3 = b3;
        if (i + 8 <= CHUNK / 4) {
            b0 = gm[q0 + i + 4]; b1 = gm[q0 + i + 5];
            b2 = gm[q0 + i + 6]; b3 = gm[q0 + i + 7];
        }
        EMIT8(c0, c1, (q0 + i) >> 1);
        EMIT8(c2, c3, ((q0 + i) >> 1) + 1);
    }
    #undef EMIT8
}

// ============================================================
// K2: HMMA band GEMM (frozen, proven 30.4us)
// ============================================================
extern __shared__ char k2_smem[];

__global__ __launch_bounds__(256, 2) void band_kernel(float* __restrict__ out)
{
    const int b   = blockIdx.y;
    const int t0  = blockIdx.x * TTILE;
    const int tid = threadIdx.x;
    const int wid = tid >> 5;
    const int lane = tid & 31;

    __half* As = reinterpret_cast<__half*>(k2_smem);             // [FPAD][AST]
    __half* Bs = reinterpret_cast<__half*>(k2_smem + A_BYTES);   // [NBn][BST]
    const uint32_t As_u = smem_u32(As);
    const uint32_t Bs_u = smem_u32(Bs);

    const size_t vbase = (size_t)b * Fn * Tn;
    #pragma unroll
    for (int it = 0; it < 17; ++it) {
        int i = tid + it * 256;
        int f = i >> 4;
        int c = i & 15;
        int t = t0 + c * 8;
        int sz = (f < Fn && t + 8 <= Tn) ? 16 : 0;
        int fc = (f < Fn) ? f : 0;
        int tc = (t + 8 <= Tn) ? t : 0;
        cpasync16(As_u + (uint32_t)((f * AST + c * 8) * 2),
                  g_vnr + vbase + (size_t)fc * Tn + tc, sz);
    }
    #pragma unroll
    for (int it = 0; it < 9; ++it) {
        int i = tid + it * 256;
        if (i < NBn * BST / 8)
            cpasync16(Bs_u + (uint32_t)(i * 16), g_fbh + i * 8, 16);
    }
    cp_commit();
    cp_wait0();
    __syncthreads();

    const int m0 = wid * 16;
    const int krow = (lane & 7) + ((lane >> 4) << 3);
    const int msel = ((lane >> 3) & 1) * 8;
    const uint32_t a_addr0 = As_u + (uint32_t)((krow * AST + m0 + msel) * 2);

    const int nrow = (lane & 7) + ((lane >> 4) << 3);
    const int ksel = ((lane >> 3) & 1) * 8;
    uint32_t b_addr0[4];
    #pragma unroll
    for (int j2 = 0; j2 < 4; ++j2)
        b_addr0[j2] = Bs_u + (uint32_t)(((j2 * 16 + nrow) * BST + ksel) * 2);

    float d[8][4];
    #pragma unroll
    for (int j = 0; j < 8; ++j)
        #pragma unroll
        for (int q = 0; q < 4; ++q) d[j][q] = 0.0f;

    for (int ks = 0; ks < KSTEPS; ++ks) {
        uint32_t a[4];
        ldsm_x4_t(a, a_addr0 + (uint32_t)(ks * 16 * AST * 2));
        #pragma unroll
        for (int j2 = 0; j2 < 4; ++j2) {
            uint32_t bbv[4];
            ldsm_x4(bbv, b_addr0[j2] + (uint32_t)(ks * 32));
            mma16816(d[j2 * 2],     a, bbv[0], bbv[1]);
            mma16816(d[j2 * 2 + 1], a, bbv[2], bbv[3]);
        }
    }

    __syncthreads();
    float* stg = reinterpret_cast<float*>(k2_smem);              // [NBn][OST]
    const int g  = lane >> 2;
    const int tp = lane & 3;
    #pragma unroll
    for (int j = 0; j < 8; ++j) {
        int n = j * 8 + 2 * tp;
        int t = m0 + g;
        stg[n * OST + t]           = d[j][0];
        stg[(n + 1) * OST + t]     = d[j][1];
        stg[n * OST + t + 8]       = d[j][2];
        stg[(n + 1) * OST + t + 8] = d[j][3];
    }
    __syncthreads();

    const int tmax = Tn - t0;
    float* ob = out + (size_t)b * NBn * Tn + t0;
    #pragma unroll
    for (int it = 0; it < 8; ++it) {
        int idx = tid + it * 256;
        int n = idx >> 5;
        int c = (idx & 31) * 4;
        if (c < tmax) {
            float4 v = *reinterpret_cast<float4*>(stg + n * OST + c);
            v.x = tanh_fast(v.x); v.y = tanh_fast(v.y);
            v.z = tanh_fast(v.z); v.w = tanh_fast(v.w);
            *reinterpret_cast<float4*>(ob + (size_t)n * Tn + c) = v;
        }
    }
}

// ============================================================
extern "C" void kernel_launch(void* const* d_in, const int* in_sizes, int n_in,
                              void* d_out, int out_size)
{
    const float* mag = (const float*)d_in[0];
    const float* fb  = (const float*)d_in[1];
    const float* ns  = (const float*)d_in[2];
    const float* rr  = (const float*)d_in[3];
    const float* rf  = (const float*)d_in[4];
    float* out = (float*)d_out;

    cudaFuncSetAttribute(band_kernel, cudaFuncAttributeMaxDynamicSharedMemorySize, SMEM_TOTAL);

    scan_kernel<<<SCAN_BLOCKS + 8, 256>>>(mag, fb, ns, rr, rf);

    dim3 grid((Tn + TTILE - 1) / TTILE, Bn);   // 63 x 16
    band_kernel<<<grid, 256, SMEM_TOTAL>>>(out);
}